// round 1
// baseline (speedup 1.0000x reference)
#include <cuda_runtime.h>
#include <cstdint>

#define D 128
#define MAXE 1000000
#define MAXN 100000

typedef unsigned long long u64;

// ---------------- scratch (device globals: no allocations allowed) ----------------
__device__ int   g_src[MAXE];
__device__ int   g_dst[MAXE];
__device__ int   g_cnt[MAXN];
__device__ float g_inv[MAXN];
__device__ float g_sums[(size_t)MAXN * D];
__device__ float g_h1[(size_t)MAXN * D];
__device__ int   g_is64;

// ---------------- index dtype detection + normalization ----------------
// int64 little-endian values in [0, 100000) have all-zero high words; int32
// random indices at odd word positions are nonzero with overwhelming probability.
__global__ void k_detect(const int* __restrict__ p) {
    int t = threadIdx.x;
    int bad = (p[2 * t + 1] != 0) ? 1 : 0;
    bad = __syncthreads_or(bad);
    if (t == 0) g_is64 = bad ? 0 : 1;
}

__global__ void k_convert(const int* __restrict__ p, int E) {
    int i = blockIdx.x * blockDim.x + threadIdx.x;
    if (i >= E) return;
    if (g_is64) {
        g_src[i] = p[2 * i];
        g_dst[i] = p[2 * E + 2 * i];
    } else {
        g_src[i] = p[i];
        g_dst[i] = p[E + i];
    }
}

// ---------------- degree count -> 1/max(cnt,1) ----------------
__global__ void k_zero_cnt(int N) {
    int i = blockIdx.x * blockDim.x + threadIdx.x;
    if (i < N) g_cnt[i] = 0;
}

__global__ void k_count(int E) {
    int i = blockIdx.x * blockDim.x + threadIdx.x;
    if (i < E) atomicAdd(&g_cnt[g_dst[i]], 1);
}

__global__ void k_inv(int N) {
    int i = blockIdx.x * blockDim.x + threadIdx.x;
    if (i < N) {
        int c = g_cnt[i];
        g_inv[i] = 1.0f / (float)(c > 0 ? c : 1);
    }
}

// ---------------- zero the sums buffer ----------------
__global__ void k_zero_sums(int n4) {
    int i = blockIdx.x * blockDim.x + threadIdx.x;
    int stride = gridDim.x * blockDim.x;
    float4 z = make_float4(0.f, 0.f, 0.f, 0.f);
    float4* p = reinterpret_cast<float4*>(g_sums);
    for (; i < n4; i += stride) p[i] = z;
}

// ---------------- edge scatter: one warp per edge, red.global.add.v4.f32 ----------------
__global__ void k_scatter(const float* __restrict__ x, int E) {
    int lane = threadIdx.x & 31;
    int w = (blockIdx.x * blockDim.x + threadIdx.x) >> 5;
    int nw = (gridDim.x * blockDim.x) >> 5;
    for (int e = w; e < E; e += nw) {
        int s = g_src[e];
        int d = g_dst[e];
        float4 v = *reinterpret_cast<const float4*>(x + (size_t)s * D + lane * 4);
        float* pd = g_sums + (size_t)d * D + lane * 4;
        asm volatile("red.global.add.v4.f32 [%0], {%1,%2,%3,%4};"
                     :: "l"(pd), "f"(v.x), "f"(v.y), "f"(v.z), "f"(v.w) : "memory");
    }
}

// ---------------- fused SAGE GEMM: Out = (sums*inv) @ Wl + b + X @ Wr, optional ReLU ----
// Tile: 128 rows x 128 cols, 256 threads, 8x8 micro-tile, packed f32x2 FMA (FFMA2).
// K is processed as two 128-chunks (aggr half with Wl, x half with Wr) so the
// weight chunk (64 KB) + duplicated-A tile (130 KB) fit in smem together.
#define TILE_M 128
#define GEMM_THREADS 256
#define SA_STRIDE 260   /* floats per k-row; 260*4=1040B keeps 16B alignment, spreads banks */
#define SW_FLOATS (128 * 128)
#define SA_FLOATS (128 * SA_STRIDE)
#define GEMM_SMEM ((SW_FLOATS + SA_FLOATS) * 4)

__device__ __forceinline__ void fma2(u64& acc, u64 a, u64 b) {
    asm("fma.rn.f32x2 %0, %1, %2, %0;" : "+l"(acc) : "l"(a), "l"(b));
}

template <bool RELU>
__global__ void __launch_bounds__(GEMM_THREADS, 1)
k_gemm(const float* __restrict__ X,
       const float* __restrict__ Wl, const float* __restrict__ Wr,
       const float* __restrict__ bias, float* __restrict__ Out, int N)
{
    extern __shared__ float smem[];
    float* sW = smem;               // [128][128]   weight chunk
    float* sA = smem + SW_FLOATS;   // [128][SA_STRIDE] duplicated pairs: sA[k][2r],sA[k][2r+1]

    const int tid = threadIdx.x;
    const int tx = tid & 15;        // 16 col groups * 8 cols
    const int ty = tid >> 4;        // 16 row groups * 8 rows
    const int c0 = tx * 8;
    const int r0 = ty * 8;
    const int n0 = blockIdx.x * TILE_M;

    u64 acc[8][4];
#pragma unroll
    for (int r = 0; r < 8; r++)
#pragma unroll
        for (int c = 0; c < 4; c++) acc[r][c] = 0ull;

#pragma unroll
    for (int chunk = 0; chunk < 2; chunk++) {
        const float* Wsrc = chunk ? Wr : Wl;
        // load weight chunk (128x128 fp32)
#pragma unroll
        for (int j = 0; j < 16; j++) {
            int idx = (j * 256 + tid) * 4;
            *reinterpret_cast<float4*>(sW + idx) =
                *reinterpret_cast<const float4*>(Wsrc + idx);
        }
        // load A tile (duplicated, k-major). 2 threads per row, 64 k each.
        {
            int r = tid >> 1;
            int half = tid & 1;
            int n = n0 + r;
            bool valid = n < N;
            const float* srcrow;
            float scale;
            if (chunk == 0) {
                srcrow = g_sums + (size_t)n * D;
                scale = valid ? g_inv[n] : 0.f;
            } else {
                srcrow = X + (size_t)n * D;
                scale = 1.f;
            }
#pragma unroll
            for (int j = 0; j < 16; j++) {
                int k = half * 64 + j * 4;
                float4 v = valid ? *reinterpret_cast<const float4*>(srcrow + k)
                                 : make_float4(0.f, 0.f, 0.f, 0.f);
                v.x *= scale; v.y *= scale; v.z *= scale; v.w *= scale;
                *reinterpret_cast<float2*>(sA + (size_t)(k + 0) * SA_STRIDE + 2 * r) = make_float2(v.x, v.x);
                *reinterpret_cast<float2*>(sA + (size_t)(k + 1) * SA_STRIDE + 2 * r) = make_float2(v.y, v.y);
                *reinterpret_cast<float2*>(sA + (size_t)(k + 2) * SA_STRIDE + 2 * r) = make_float2(v.z, v.z);
                *reinterpret_cast<float2*>(sA + (size_t)(k + 3) * SA_STRIDE + 2 * r) = make_float2(v.w, v.w);
            }
        }
        __syncthreads();

#pragma unroll 2
        for (int k = 0; k < 128; k++) {
            const ulonglong2* ap = reinterpret_cast<const ulonglong2*>(sA + (size_t)k * SA_STRIDE + 2 * r0);
            const ulonglong2* wp = reinterpret_cast<const ulonglong2*>(sW + k * 128 + c0);
            ulonglong2 a01 = ap[0], a23 = ap[1], a45 = ap[2], a67 = ap[3];
            ulonglong2 w01 = wp[0], w23 = wp[1];
            u64 av[8] = {a01.x, a01.y, a23.x, a23.y, a45.x, a45.y, a67.x, a67.y};
            u64 wv[4] = {w01.x, w01.y, w23.x, w23.y};
#pragma unroll
            for (int r = 0; r < 8; r++)
#pragma unroll
                for (int c = 0; c < 4; c++)
                    fma2(acc[r][c], av[r], wv[c]);
        }
        __syncthreads();
    }

    // epilogue: +bias, optional relu, store
    float bv[8];
#pragma unroll
    for (int q = 0; q < 8; q++) bv[q] = bias[c0 + q];

#pragma unroll
    for (int r = 0; r < 8; r++) {
        int n = n0 + r0 + r;
        if (n < N) {
            float o[8];
#pragma unroll
            for (int c = 0; c < 4; c++) {
                union { u64 u; float2 f; } cvt;
                cvt.u = acc[r][c];
                o[2 * c + 0] = cvt.f.x + bv[2 * c + 0];
                o[2 * c + 1] = cvt.f.y + bv[2 * c + 1];
            }
            if (RELU) {
#pragma unroll
                for (int q = 0; q < 8; q++) o[q] = fmaxf(o[q], 0.f);
            }
            float* outp = Out + (size_t)n * D + c0;
            *reinterpret_cast<float4*>(outp + 0) = make_float4(o[0], o[1], o[2], o[3]);
            *reinterpret_cast<float4*>(outp + 4) = make_float4(o[4], o[5], o[6], o[7]);
        }
    }
}

// ---------------- launch ----------------
extern "C" void kernel_launch(void* const* d_in, const int* in_sizes, int n_in,
                              void* d_out, int out_size) {
    const int*   edge     = (const int*)d_in[0];
    const float* node_emb = (const float*)d_in[1];
    const float* w1l      = (const float*)d_in[2];
    const float* b1       = (const float*)d_in[3];
    const float* w1r      = (const float*)d_in[4];
    const float* w2l      = (const float*)d_in[5];
    const float* b2       = (const float*)d_in[6];
    const float* w2r      = (const float*)d_in[7];
    float*       out      = (float*)d_out;

    const int E = in_sizes[0] / 2;   // element count is 2*E for both int32 and int64 metadata
    const int N = in_sizes[1] / D;

    cudaFuncSetAttribute(k_gemm<true>,  cudaFuncAttributeMaxDynamicSharedMemorySize, GEMM_SMEM);
    cudaFuncSetAttribute(k_gemm<false>, cudaFuncAttributeMaxDynamicSharedMemorySize, GEMM_SMEM);

    float* h1ptr = nullptr;
    cudaGetSymbolAddress((void**)&h1ptr, g_h1);

    // edge index normalization (dtype-agnostic) + degrees
    k_detect<<<1, 256>>>(edge);
    k_convert<<<(E + 255) / 256, 256>>>(edge, E);
    k_zero_cnt<<<(N + 255) / 256, 256>>>(N);
    k_count<<<(E + 255) / 256, 256>>>(E);
    k_inv<<<(N + 255) / 256, 256>>>(N);

    const int n4 = (N * D) / 4;
    const int tiles = (N + TILE_M - 1) / TILE_M;

    // layer 1
    k_zero_sums<<<1184, 256>>>(n4);
    k_scatter<<<4440, 256>>>(node_emb, E);
    k_gemm<true><<<tiles, GEMM_THREADS, GEMM_SMEM>>>(node_emb, w1l, w1r, b1, h1ptr, N);

    // layer 2
    k_zero_sums<<<1184, 256>>>(n4);
    k_scatter<<<4440, 256>>>(h1ptr, E);
    k_gemm<false><<<tiles, GEMM_THREADS, GEMM_SMEM>>>(h1ptr, w2l, w2r, b2, out, N);
}

// round 2
// speedup vs baseline: 1.1957x; 1.1957x over previous
#include <cuda_runtime.h>
#include <cstdint>

#define D 128
#define MAXE 1000000
#define MAXN 100000

typedef unsigned long long u64;

// ---------------- scratch (device globals: no allocations allowed) ----------------
__device__ int   g_src[MAXE];
__device__ int   g_dst[MAXE];
__device__ int   g_csr[MAXE];          // src ids grouped by dst
__device__ int   g_cnt[MAXN];
__device__ int   g_off[MAXN + 1];      // exclusive prefix of cnt
__device__ int   g_cursor[MAXN];
__device__ int   g_bsum[128];
__device__ int   g_boff[128];
__device__ float g_sums[(size_t)MAXN * D];
__device__ float g_h1[(size_t)MAXN * D];
__device__ int   g_is64;

// ---------------- index dtype detection ----------------
__global__ void k_detect(const int* __restrict__ p) {
    int t = threadIdx.x;
    int bad = (p[2 * t + 1] != 0) ? 1 : 0;
    bad = __syncthreads_or(bad);
    if (t == 0) g_is64 = bad ? 0 : 1;
}

__global__ void k_zero_cnt(int N) {
    int i = blockIdx.x * blockDim.x + threadIdx.x;
    if (i < N) g_cnt[i] = 0;
}

// convert (int64 or int32 -> int32) + degree count in one pass
__global__ void k_convert_count(const int* __restrict__ p, int E) {
    int i = blockIdx.x * blockDim.x + threadIdx.x;
    if (i >= E) return;
    int s, d;
    if (g_is64) { s = p[2 * i]; d = p[2 * E + 2 * i]; }
    else        { s = p[i];     d = p[E + i]; }
    g_src[i] = s;
    g_dst[i] = d;
    atomicAdd(&g_cnt[d], 1);
}

// ---------------- 3-kernel exclusive scan of g_cnt -> g_off ----------------
#define SCAN_BLOCK 1024

__global__ void k_blocksum(int N) {
    __shared__ int sh[SCAN_BLOCK];
    int i = blockIdx.x * SCAN_BLOCK + threadIdx.x;
    int v = (i < N) ? g_cnt[i] : 0;
    sh[threadIdx.x] = v;
    __syncthreads();
    for (int s = SCAN_BLOCK / 2; s > 0; s >>= 1) {
        if (threadIdx.x < s) sh[threadIdx.x] += sh[threadIdx.x + s];
        __syncthreads();
    }
    if (threadIdx.x == 0) g_bsum[blockIdx.x] = sh[0];
}

__global__ void k_scan_bsums(int nblk, int N, int E) {
    if (threadIdx.x == 0) {
        int run = 0;
        for (int b = 0; b < nblk; b++) { g_boff[b] = run; run += g_bsum[b]; }
        g_off[N] = E;
    }
}

__global__ void k_scan_final(int N) {
    __shared__ int sh[SCAN_BLOCK];
    int i = blockIdx.x * SCAN_BLOCK + threadIdx.x;
    int v = (i < N) ? g_cnt[i] : 0;
    sh[threadIdx.x] = v;
    __syncthreads();
    // Hillis-Steele inclusive scan
#pragma unroll
    for (int s = 1; s < SCAN_BLOCK; s <<= 1) {
        int t = (threadIdx.x >= s) ? sh[threadIdx.x - s] : 0;
        __syncthreads();
        sh[threadIdx.x] += t;
        __syncthreads();
    }
    if (i < N) {
        int excl = g_boff[blockIdx.x] + sh[threadIdx.x] - v;
        g_off[i] = excl;
        g_cursor[i] = excl;
    }
}

// ---------------- CSR fill ----------------
__global__ void k_fill(int E) {
    int i = blockIdx.x * blockDim.x + threadIdx.x;
    if (i >= E) return;
    int d = g_dst[i];
    int pos = atomicAdd(&g_cursor[d], 1);
    g_csr[pos] = g_src[i];
}

// ---------------- aggregation: one warp per dst node, mean of neighbor rows ----------------
__global__ void k_aggr(const float* __restrict__ x, float* __restrict__ out, int N) {
    int warp = (blockIdx.x * blockDim.x + threadIdx.x) >> 5;
    if (warp >= N) return;
    int lane = threadIdx.x & 31;
    int beg = g_off[warp];
    int end = g_off[warp + 1];
    const int c = lane * 4;
    float4 acc = make_float4(0.f, 0.f, 0.f, 0.f);
    int i = beg;
    for (; i + 4 <= end; i += 4) {
        int s0 = g_csr[i], s1 = g_csr[i + 1], s2 = g_csr[i + 2], s3 = g_csr[i + 3];
        float4 v0 = *reinterpret_cast<const float4*>(x + (size_t)s0 * D + c);
        float4 v1 = *reinterpret_cast<const float4*>(x + (size_t)s1 * D + c);
        float4 v2 = *reinterpret_cast<const float4*>(x + (size_t)s2 * D + c);
        float4 v3 = *reinterpret_cast<const float4*>(x + (size_t)s3 * D + c);
        acc.x += v0.x; acc.y += v0.y; acc.z += v0.z; acc.w += v0.w;
        acc.x += v1.x; acc.y += v1.y; acc.z += v1.z; acc.w += v1.w;
        acc.x += v2.x; acc.y += v2.y; acc.z += v2.z; acc.w += v2.w;
        acc.x += v3.x; acc.y += v3.y; acc.z += v3.z; acc.w += v3.w;
    }
    for (; i < end; i++) {
        int s = g_csr[i];
        float4 v = *reinterpret_cast<const float4*>(x + (size_t)s * D + c);
        acc.x += v.x; acc.y += v.y; acc.z += v.z; acc.w += v.w;
    }
    int deg = end - beg;
    float inv = 1.f / (float)(deg > 0 ? deg : 1);
    acc.x *= inv; acc.y *= inv; acc.z *= inv; acc.w *= inv;
    *reinterpret_cast<float4*>(out + (size_t)warp * D + c) = acc;
}

// ---------------- fused SAGE GEMM: Out = aggr @ Wl + b + X @ Wr, optional ReLU ----
#define TILE_M 128
#define GEMM_THREADS 256
#define SA_STRIDE 260
#define SW_FLOATS (128 * 128)
#define SA_FLOATS (128 * SA_STRIDE)
#define GEMM_SMEM ((SW_FLOATS + SA_FLOATS) * 4)

__device__ __forceinline__ void fma2(u64& acc, u64 a, u64 b) {
    asm("fma.rn.f32x2 %0, %1, %2, %0;" : "+l"(acc) : "l"(a), "l"(b));
}

template <bool RELU>
__global__ void __launch_bounds__(GEMM_THREADS, 1)
k_gemm(const float* __restrict__ X,
       const float* __restrict__ Wl, const float* __restrict__ Wr,
       const float* __restrict__ bias, float* __restrict__ Out, int N)
{
    extern __shared__ float smem[];
    float* sW = smem;               // [128][128] weight chunk
    float* sA = smem + SW_FLOATS;   // [128][SA_STRIDE] duplicated pairs

    const int tid = threadIdx.x;
    const int tx = tid & 15;
    const int ty = tid >> 4;
    const int c0 = tx * 8;
    const int r0 = ty * 8;
    const int n0 = blockIdx.x * TILE_M;

    u64 acc[8][4];
#pragma unroll
    for (int r = 0; r < 8; r++)
#pragma unroll
        for (int c = 0; c < 4; c++) acc[r][c] = 0ull;

#pragma unroll
    for (int chunk = 0; chunk < 2; chunk++) {
        const float* Wsrc = chunk ? Wr : Wl;
#pragma unroll
        for (int j = 0; j < 16; j++) {
            int idx = (j * 256 + tid) * 4;
            *reinterpret_cast<float4*>(sW + idx) =
                *reinterpret_cast<const float4*>(Wsrc + idx);
        }
        {
            int r = tid >> 1;
            int half = tid & 1;
            int n = n0 + r;
            bool valid = n < N;
            const float* srcrow = (chunk == 0) ? (g_sums + (size_t)n * D)
                                               : (X + (size_t)n * D);
#pragma unroll
            for (int j = 0; j < 16; j++) {
                int k = half * 64 + j * 4;
                float4 v = valid ? *reinterpret_cast<const float4*>(srcrow + k)
                                 : make_float4(0.f, 0.f, 0.f, 0.f);
                *reinterpret_cast<float2*>(sA + (size_t)(k + 0) * SA_STRIDE + 2 * r) = make_float2(v.x, v.x);
                *reinterpret_cast<float2*>(sA + (size_t)(k + 1) * SA_STRIDE + 2 * r) = make_float2(v.y, v.y);
                *reinterpret_cast<float2*>(sA + (size_t)(k + 2) * SA_STRIDE + 2 * r) = make_float2(v.z, v.z);
                *reinterpret_cast<float2*>(sA + (size_t)(k + 3) * SA_STRIDE + 2 * r) = make_float2(v.w, v.w);
            }
        }
        __syncthreads();

#pragma unroll 2
        for (int k = 0; k < 128; k++) {
            const ulonglong2* ap = reinterpret_cast<const ulonglong2*>(sA + (size_t)k * SA_STRIDE + 2 * r0);
            const ulonglong2* wp = reinterpret_cast<const ulonglong2*>(sW + k * 128 + c0);
            ulonglong2 a01 = ap[0], a23 = ap[1], a45 = ap[2], a67 = ap[3];
            ulonglong2 w01 = wp[0], w23 = wp[1];
            u64 av[8] = {a01.x, a01.y, a23.x, a23.y, a45.x, a45.y, a67.x, a67.y};
            u64 wv[4] = {w01.x, w01.y, w23.x, w23.y};
#pragma unroll
            for (int r = 0; r < 8; r++)
#pragma unroll
                for (int c = 0; c < 4; c++)
                    fma2(acc[r][c], av[r], wv[c]);
        }
        __syncthreads();
    }

    float bv[8];
#pragma unroll
    for (int q = 0; q < 8; q++) bv[q] = bias[c0 + q];

#pragma unroll
    for (int r = 0; r < 8; r++) {
        int n = n0 + r0 + r;
        if (n < N) {
            float o[8];
#pragma unroll
            for (int c = 0; c < 4; c++) {
                union { u64 u; float2 f; } cvt;
                cvt.u = acc[r][c];
                o[2 * c + 0] = cvt.f.x + bv[2 * c + 0];
                o[2 * c + 1] = cvt.f.y + bv[2 * c + 1];
            }
            if (RELU) {
#pragma unroll
                for (int q = 0; q < 8; q++) o[q] = fmaxf(o[q], 0.f);
            }
            float* outp = Out + (size_t)n * D + c0;
            *reinterpret_cast<float4*>(outp + 0) = make_float4(o[0], o[1], o[2], o[3]);
            *reinterpret_cast<float4*>(outp + 4) = make_float4(o[4], o[5], o[6], o[7]);
        }
    }
}

// ---------------- launch ----------------
extern "C" void kernel_launch(void* const* d_in, const int* in_sizes, int n_in,
                              void* d_out, int out_size) {
    const int*   edge     = (const int*)d_in[0];
    const float* node_emb = (const float*)d_in[1];
    const float* w1l      = (const float*)d_in[2];
    const float* b1       = (const float*)d_in[3];
    const float* w1r      = (const float*)d_in[4];
    const float* w2l      = (const float*)d_in[5];
    const float* b2       = (const float*)d_in[6];
    const float* w2r      = (const float*)d_in[7];
    float*       out      = (float*)d_out;

    const int E = in_sizes[0] / 2;
    const int N = in_sizes[1] / D;

    cudaFuncSetAttribute(k_gemm<true>,  cudaFuncAttributeMaxDynamicSharedMemorySize, GEMM_SMEM);
    cudaFuncSetAttribute(k_gemm<false>, cudaFuncAttributeMaxDynamicSharedMemorySize, GEMM_SMEM);

    float* h1ptr = nullptr;
    cudaGetSymbolAddress((void**)&h1ptr, g_h1);
    float* sumsptr = nullptr;
    cudaGetSymbolAddress((void**)&sumsptr, g_sums);

    const int nblk_scan = (N + SCAN_BLOCK - 1) / SCAN_BLOCK;
    const int tiles = (N + TILE_M - 1) / TILE_M;
    const int aggr_blocks = (N * 32 + 255) / 256;

    // ---- CSR build (once per launch) ----
    k_detect<<<1, 256>>>(edge);
    k_zero_cnt<<<(N + 255) / 256, 256>>>(N);
    k_convert_count<<<(E + 255) / 256, 256>>>(edge, E);
    k_blocksum<<<nblk_scan, SCAN_BLOCK>>>(N);
    k_scan_bsums<<<1, 32>>>(nblk_scan, N, E);
    k_scan_final<<<nblk_scan, SCAN_BLOCK>>>(N);
    k_fill<<<(E + 255) / 256, 256>>>(E);

    // ---- layer 1 ----
    k_aggr<<<aggr_blocks, 256>>>(node_emb, sumsptr, N);
    k_gemm<true><<<tiles, GEMM_THREADS, GEMM_SMEM>>>(node_emb, w1l, w1r, b1, h1ptr, N);

    // ---- layer 2 ----
    k_aggr<<<aggr_blocks, 256>>>(h1ptr, sumsptr, N);
    k_gemm<false><<<tiles, GEMM_THREADS, GEMM_SMEM>>>(h1ptr, w2l, w2r, b2, out, N);
}

// round 4
// speedup vs baseline: 1.7239x; 1.4418x over previous
#include <cuda_runtime.h>
#include <cuda_bf16.h>
#include <cstdint>

#define D 128
#define MAXE 1000000
#define MAXN 100000

typedef unsigned long long u64;

// ================= scratch =================
__device__ int   g_src[MAXE];
__device__ int   g_dst[MAXE];
__device__ int   g_csr[MAXE];
__device__ int   g_cnt[MAXN];
__device__ int   g_off[MAXN + 1];
__device__ int   g_cursor[MAXN];
__device__ int   g_bsum[128];
__device__ int   g_boff[128];
__device__ float g_h1[(size_t)MAXN * D];
__device__ __nv_bfloat16 g_Ahi[(size_t)MAXN * 256];
__device__ __nv_bfloat16 g_Alo[(size_t)MAXN * 256];
__device__ __nv_bfloat16 g_B1hi[128 * 256];
__device__ __nv_bfloat16 g_B1lo[128 * 256];
__device__ __nv_bfloat16 g_B2hi[128 * 256];
__device__ __nv_bfloat16 g_B2lo[128 * 256];
__device__ int   g_is64;

// ================= CSR build =================
__global__ void k_detect(const int* __restrict__ p) {
    int t = threadIdx.x;
    int bad = (p[2 * t + 1] != 0) ? 1 : 0;
    bad = __syncthreads_or(bad);
    if (t == 0) g_is64 = bad ? 0 : 1;
}
__global__ void k_zero_cnt(int N) {
    int i = blockIdx.x * blockDim.x + threadIdx.x;
    if (i < N) g_cnt[i] = 0;
}
__global__ void k_convert_count(const int* __restrict__ p, int E) {
    int i = blockIdx.x * blockDim.x + threadIdx.x;
    if (i >= E) return;
    int s, d;
    if (g_is64) { s = p[2 * i]; d = p[2 * E + 2 * i]; }
    else        { s = p[i];     d = p[E + i]; }
    g_src[i] = s; g_dst[i] = d;
    atomicAdd(&g_cnt[d], 1);
}

#define SCAN_BLOCK 1024
__global__ void k_blocksum(int N) {
    __shared__ int sh[SCAN_BLOCK];
    int i = blockIdx.x * SCAN_BLOCK + threadIdx.x;
    sh[threadIdx.x] = (i < N) ? g_cnt[i] : 0;
    __syncthreads();
    for (int s = SCAN_BLOCK / 2; s > 0; s >>= 1) {
        if (threadIdx.x < s) sh[threadIdx.x] += sh[threadIdx.x + s];
        __syncthreads();
    }
    if (threadIdx.x == 0) g_bsum[blockIdx.x] = sh[0];
}
__global__ void k_scan_bsums(int nblk, int N, int E) {
    if (threadIdx.x == 0) {
        int run = 0;
        for (int b = 0; b < nblk; b++) { g_boff[b] = run; run += g_bsum[b]; }
        g_off[N] = E;
    }
}
__global__ void k_scan_final(int N) {
    __shared__ int sh[SCAN_BLOCK];
    int i = blockIdx.x * SCAN_BLOCK + threadIdx.x;
    int v = (i < N) ? g_cnt[i] : 0;
    sh[threadIdx.x] = v;
    __syncthreads();
#pragma unroll
    for (int s = 1; s < SCAN_BLOCK; s <<= 1) {
        int t = (threadIdx.x >= s) ? sh[threadIdx.x - s] : 0;
        __syncthreads();
        sh[threadIdx.x] += t;
        __syncthreads();
    }
    if (i < N) {
        int excl = g_boff[blockIdx.x] + sh[threadIdx.x] - v;
        g_off[i] = excl;
        g_cursor[i] = excl;
    }
}
__global__ void k_fill(int E) {
    int i = blockIdx.x * blockDim.x + threadIdx.x;
    if (i >= E) return;
    int d = g_dst[i];
    g_csr[atomicAdd(&g_cursor[d], 1)] = g_src[i];
}

// ================= weight transpose + bf16 hi/lo split =================
__device__ __forceinline__ void split_bf(float v, __nv_bfloat16& hi, __nv_bfloat16& lo) {
    hi = __float2bfloat16(v);
    lo = __float2bfloat16(v - __bfloat162float(hi));
}
__global__ void k_convw(const float* __restrict__ Wl, const float* __restrict__ Wr,
                        __nv_bfloat16* __restrict__ Bhi, __nv_bfloat16* __restrict__ Blo) {
    int t = blockIdx.x * blockDim.x + threadIdx.x;
    if (t >= 128 * 128) return;
    int k = t >> 7, n = t & 127;
    __nv_bfloat16 h, l;
    split_bf(Wl[k * 128 + n], h, l);
    Bhi[n * 256 + k] = h; Blo[n * 256 + k] = l;
    split_bf(Wr[k * 128 + n], h, l);
    Bhi[n * 256 + 128 + k] = h; Blo[n * 256 + 128 + k] = l;
}

// ================= aggregation: CSR mean + emit A (bf16 hi/lo) =================
// A row layout: [0..127] = mean of neighbors, [128..255] = x row
__global__ void k_aggr(const float* __restrict__ x, int N) {
    int warp = (blockIdx.x * blockDim.x + threadIdx.x) >> 5;
    if (warp >= N) return;
    int lane = threadIdx.x & 31;
    int beg = g_off[warp];
    int end = g_off[warp + 1];
    const int c = lane * 4;
    float4 acc = make_float4(0.f, 0.f, 0.f, 0.f);
    int i = beg;
    for (; i + 4 <= end; i += 4) {
        int s0 = g_csr[i], s1 = g_csr[i + 1], s2 = g_csr[i + 2], s3 = g_csr[i + 3];
        float4 v0 = *reinterpret_cast<const float4*>(x + (size_t)s0 * D + c);
        float4 v1 = *reinterpret_cast<const float4*>(x + (size_t)s1 * D + c);
        float4 v2 = *reinterpret_cast<const float4*>(x + (size_t)s2 * D + c);
        float4 v3 = *reinterpret_cast<const float4*>(x + (size_t)s3 * D + c);
        acc.x += v0.x + v1.x + v2.x + v3.x;
        acc.y += v0.y + v1.y + v2.y + v3.y;
        acc.z += v0.z + v1.z + v2.z + v3.z;
        acc.w += v0.w + v1.w + v2.w + v3.w;
    }
    for (; i < end; i++) {
        int s = g_csr[i];
        float4 v = *reinterpret_cast<const float4*>(x + (size_t)s * D + c);
        acc.x += v.x; acc.y += v.y; acc.z += v.z; acc.w += v.w;
    }
    int deg = end - beg;
    float inv = 1.f / (float)(deg > 0 ? deg : 1);
    acc.x *= inv; acc.y *= inv; acc.z *= inv; acc.w *= inv;

    {
        __nv_bfloat16 h[4], l[4];
        split_bf(acc.x, h[0], l[0]); split_bf(acc.y, h[1], l[1]);
        split_bf(acc.z, h[2], l[2]); split_bf(acc.w, h[3], l[3]);
        *reinterpret_cast<uint2*>(g_Ahi + (size_t)warp * 256 + c) = *reinterpret_cast<uint2*>(h);
        *reinterpret_cast<uint2*>(g_Alo + (size_t)warp * 256 + c) = *reinterpret_cast<uint2*>(l);
    }
    {
        float4 xv = *reinterpret_cast<const float4*>(x + (size_t)warp * D + c);
        __nv_bfloat16 h[4], l[4];
        split_bf(xv.x, h[0], l[0]); split_bf(xv.y, h[1], l[1]);
        split_bf(xv.z, h[2], l[2]); split_bf(xv.w, h[3], l[3]);
        *reinterpret_cast<uint2*>(g_Ahi + (size_t)warp * 256 + 128 + c) = *reinterpret_cast<uint2*>(h);
        *reinterpret_cast<uint2*>(g_Alo + (size_t)warp * 256 + 128 + c) = *reinterpret_cast<uint2*>(l);
    }
}

// ================= mma.sync GEMM: Out = A @ B^T + bias (opt ReLU) =================
// A: [M][256] bf16 hi/lo, B: [128][256] bf16 hi/lo (n-major => col-major for B^T)
// D = Ahi.Bhi + Ahi.Blo + Alo.Bhi, fp32 accum. Tile 128x128, K chunk 2x128.
#define GT 256
#define SAK 136                         // padded smem stride (elements)
#define SROW (SAK * 2)                  // 272 bytes per row
#define CH_BYTES (128 * SROW)           // 34816 B per operand chunk
#define OFF_AHI 0
#define OFF_ALO (CH_BYTES)
#define OFF_BHI (2 * CH_BYTES)
#define OFF_BLO (3 * CH_BYTES)
#define SM_TOTAL (4 * CH_BYTES)         // 139264 B

__device__ __forceinline__ uint32_t smem_u32(const void* p) {
    uint32_t a;
    asm("{ .reg .u64 t; cvta.to.shared.u64 t, %1; cvt.u32.u64 %0, t; }" : "=r"(a) : "l"(p));
    return a;
}
__device__ __forceinline__ void ldsm_x4(uint32_t* r, uint32_t addr) {
    asm volatile("ldmatrix.sync.aligned.m8n8.x4.shared.b16 {%0,%1,%2,%3}, [%4];"
                 : "=r"(r[0]), "=r"(r[1]), "=r"(r[2]), "=r"(r[3]) : "r"(addr));
}
__device__ __forceinline__ void mma16816(float* c, const uint32_t* a, const uint32_t* b) {
    asm volatile(
        "mma.sync.aligned.m16n8k16.row.col.f32.bf16.bf16.f32 "
        "{%0,%1,%2,%3}, {%4,%5,%6,%7}, {%8,%9}, {%0,%1,%2,%3};"
        : "+f"(c[0]), "+f"(c[1]), "+f"(c[2]), "+f"(c[3])
        : "r"(a[0]), "r"(a[1]), "r"(a[2]), "r"(a[3]), "r"(b[0]), "r"(b[1]));
}

template <bool RELU>
__global__ void __launch_bounds__(GT, 1)
k_mma(const __nv_bfloat16* __restrict__ Ahi, const __nv_bfloat16* __restrict__ Alo,
      const __nv_bfloat16* __restrict__ Bhi, const __nv_bfloat16* __restrict__ Blo,
      const float* __restrict__ bias, float* __restrict__ Out, int N)
{
    extern __shared__ char smem[];
    const uint32_t sb = smem_u32(smem);
    const int tid = threadIdx.x;
    const int wid = tid >> 5, lane = tid & 31;
    const int wm = wid >> 1, wn = wid & 1;      // 4x2 warp grid: 32 rows x 64 cols each
    const int n0 = blockIdx.x * 128;

    float acc[2][8][4];
#pragma unroll
    for (int mf = 0; mf < 2; mf++)
#pragma unroll
        for (int nf = 0; nf < 8; nf++)
#pragma unroll
            for (int q = 0; q < 4; q++) acc[mf][nf][q] = 0.f;

    const int lrow = tid >> 1;        // 0..127 (smem row for loads)
    const int lseg = tid & 1;

    // ldmatrix base offsets (byte offsets within an operand chunk)
    const uint32_t a_off = (uint32_t)(wm * 32 + (lane & 15)) * SROW + (uint32_t)(lane >> 4) * 16;
    const uint32_t b_row = (uint32_t)(wn * 64 + (lane & 7) + (((lane >> 4) & 1) << 3));
    const uint32_t b_off = b_row * SROW + (uint32_t)((lane >> 3) & 1) * 16;

#pragma unroll
    for (int chunk = 0; chunk < 2; chunk++) {
        const int kofs = chunk * 128;
        // ---- load 4 operand chunks into padded smem ----
#pragma unroll
        for (int j = 0; j < 8; j++) {
            int c16 = lseg * 8 + j;                       // 16B unit within 256B of chunk row
            uint32_t so = (uint32_t)lrow * SROW + (uint32_t)c16 * 16;
            int grow = n0 + lrow;
            uint4 z = make_uint4(0, 0, 0, 0);
            size_t ga = (size_t)grow * 256 + kofs + c16 * 8;
            uint4 vh = (grow < N) ? *reinterpret_cast<const uint4*>(Ahi + ga) : z;
            uint4 vl = (grow < N) ? *reinterpret_cast<const uint4*>(Alo + ga) : z;
            size_t gb = (size_t)lrow * 256 + kofs + c16 * 8;
            uint4 wh = *reinterpret_cast<const uint4*>(Bhi + gb);
            uint4 wl = *reinterpret_cast<const uint4*>(Blo + gb);
            *reinterpret_cast<uint4*>(smem + OFF_AHI + so) = vh;
            *reinterpret_cast<uint4*>(smem + OFF_ALO + so) = vl;
            *reinterpret_cast<uint4*>(smem + OFF_BHI + so) = wh;
            *reinterpret_cast<uint4*>(smem + OFF_BLO + so) = wl;
        }
        __syncthreads();

#pragma unroll
        for (int term = 0; term < 3; term++) {
            const uint32_t sA = sb + (term == 2 ? OFF_ALO : OFF_AHI);
            const uint32_t sB = sb + (term == 1 ? OFF_BLO : OFF_BHI);
#pragma unroll
            for (int ks = 0; ks < 8; ks++) {
                const uint32_t kb = (uint32_t)ks * 32;    // 16 elems = 32 B
                uint32_t af[2][4];
                ldsm_x4(af[0], sA + a_off + kb);
                ldsm_x4(af[1], sA + a_off + 16 * SROW + kb);
                uint32_t bf[8][2];
#pragma unroll
                for (int nb = 0; nb < 4; nb++) {
                    uint32_t r[4];
                    ldsm_x4(r, sB + b_off + (uint32_t)nb * 16 * SROW + kb);
                    bf[nb * 2][0] = r[0]; bf[nb * 2][1] = r[1];
                    bf[nb * 2 + 1][0] = r[2]; bf[nb * 2 + 1][1] = r[3];
                }
#pragma unroll
                for (int mf = 0; mf < 2; mf++)
#pragma unroll
                    for (int nf = 0; nf < 8; nf++)
                        mma16816(acc[mf][nf], af[mf], bf[nf]);
            }
        }
        __syncthreads();
    }

    // ---- epilogue: bias + opt relu, direct global store ----
    const int gid = lane >> 2, t4 = lane & 3;
#pragma unroll
    for (int nf = 0; nf < 8; nf++) {
        int col = wn * 64 + nf * 8 + t4 * 2;
        float b0 = __ldg(bias + col), b1 = __ldg(bias + col + 1);
#pragma unroll
        for (int mf = 0; mf < 2; mf++) {
            int m0 = n0 + wm * 32 + mf * 16 + gid;
            if (m0 < N) {
                float2 o = make_float2(acc[mf][nf][0] + b0, acc[mf][nf][1] + b1);
                if (RELU) { o.x = fmaxf(o.x, 0.f); o.y = fmaxf(o.y, 0.f); }
                *reinterpret_cast<float2*>(Out + (size_t)m0 * D + col) = o;
            }
            int m1 = m0 + 8;
            if (m1 < N) {
                float2 o = make_float2(acc[mf][nf][2] + b0, acc[mf][nf][3] + b1);
                if (RELU) { o.x = fmaxf(o.x, 0.f); o.y = fmaxf(o.y, 0.f); }
                *reinterpret_cast<float2*>(Out + (size_t)m1 * D + col) = o;
            }
        }
    }
}

// ================= launch =================
extern "C" void kernel_launch(void* const* d_in, const int* in_sizes, int n_in,
                              void* d_out, int out_size) {
    const int*   edge     = (const int*)d_in[0];
    const float* node_emb = (const float*)d_in[1];
    const float* w1l      = (const float*)d_in[2];
    const float* b1       = (const float*)d_in[3];
    const float* w1r      = (const float*)d_in[4];
    const float* w2l      = (const float*)d_in[5];
    const float* b2       = (const float*)d_in[6];
    const float* w2r      = (const float*)d_in[7];
    float*       out      = (float*)d_out;

    const int E = in_sizes[0] / 2;
    const int N = in_sizes[1] / D;

    cudaFuncSetAttribute(k_mma<true>,  cudaFuncAttributeMaxDynamicSharedMemorySize, SM_TOTAL);
    cudaFuncSetAttribute(k_mma<false>, cudaFuncAttributeMaxDynamicSharedMemorySize, SM_TOTAL);

    float* h1ptr = nullptr;  cudaGetSymbolAddress((void**)&h1ptr, g_h1);
    __nv_bfloat16 *ahi, *alo, *b1hi, *b1lo, *b2hi, *b2lo;
    cudaGetSymbolAddress((void**)&ahi, g_Ahi);
    cudaGetSymbolAddress((void**)&alo, g_Alo);
    cudaGetSymbolAddress((void**)&b1hi, g_B1hi);
    cudaGetSymbolAddress((void**)&b1lo, g_B1lo);
    cudaGetSymbolAddress((void**)&b2hi, g_B2hi);
    cudaGetSymbolAddress((void**)&b2lo, g_B2lo);

    const int nblk_scan = (N + SCAN_BLOCK - 1) / SCAN_BLOCK;
    const int tiles = (N + 127) / 128;
    const int aggr_blocks = (N * 32 + 255) / 256;

    // ---- CSR build + weight prep ----
    k_detect<<<1, 256>>>(edge);
    k_zero_cnt<<<(N + 255) / 256, 256>>>(N);
    k_convert_count<<<(E + 255) / 256, 256>>>(edge, E);
    k_blocksum<<<nblk_scan, SCAN_BLOCK>>>(N);
    k_scan_bsums<<<1, 32>>>(nblk_scan, N, E);
    k_scan_final<<<nblk_scan, SCAN_BLOCK>>>(N);
    k_fill<<<(E + 255) / 256, 256>>>(E);
    k_convw<<<64, 256>>>(w1l, w1r, b1hi, b1lo);
    k_convw<<<64, 256>>>(w2l, w2r, b2hi, b2lo);

    // ---- layer 1 ----
    k_aggr<<<aggr_blocks, 256>>>(node_emb, N);
    k_mma<true><<<tiles, GT, SM_TOTAL>>>(ahi, alo, b1hi, b1lo, b1, h1ptr, N);

    // ---- layer 2 ----
    k_aggr<<<aggr_blocks, 256>>>(h1ptr, N);
    k_mma<false><<<tiles, GT, SM_TOTAL>>>(ahi, alo, b2hi, b2lo, b2, out, N);
}

// round 5
// speedup vs baseline: 1.7330x; 1.0053x over previous
#include <cuda_runtime.h>
#include <cuda_bf16.h>
#include <cstdint>

#define D 128
#define MAXE 1000000
#define MAXN 100000

typedef unsigned long long u64;

// ================= scratch =================
__device__ int      g_src[MAXE];
__device__ int      g_dst[MAXE];
__device__ int      g_csr[MAXE];
__device__ int      g_cnt[MAXN];
__device__ int      g_off[MAXN + 1];
__device__ int      g_cursor[MAXN];
__device__ int      g_bsum[128];
__device__ uint32_t g_Xp[(size_t)MAXN * D];    // packed (hi | lo<<16) input features
__device__ uint32_t g_X2p[(size_t)MAXN * D];   // packed relu(h1)
__device__ uint32_t g_Gp[(size_t)MAXN * D];    // packed aggregates
__device__ __nv_bfloat16 g_B1hi[128 * 256];
__device__ __nv_bfloat16 g_B1lo[128 * 256];
__device__ __nv_bfloat16 g_B2hi[128 * 256];
__device__ __nv_bfloat16 g_B2lo[128 * 256];
__device__ int      g_is64;

// ================= packing helpers =================
__device__ __forceinline__ uint32_t packv(float v) {
    unsigned short h = __bfloat16_as_ushort(__float2bfloat16(v));
    float r = v - __uint_as_float((uint32_t)h << 16);
    unsigned short l = __bfloat16_as_ushort(__float2bfloat16(r));
    return (uint32_t)h | ((uint32_t)l << 16);
}
__device__ __forceinline__ float unpackv(uint32_t p) {
    return __uint_as_float(p << 16) + __uint_as_float(p & 0xFFFF0000u);
}
__device__ __forceinline__ void split_bf(float v, __nv_bfloat16& hi, __nv_bfloat16& lo) {
    hi = __float2bfloat16(v);
    lo = __float2bfloat16(v - __bfloat162float(hi));
}

// ================= fused prep: convw x2 + convx + zero_cnt + detect ==========
__global__ void k_prep(const float* __restrict__ ne,
                       const float* __restrict__ w1l, const float* __restrict__ w1r,
                       const float* __restrict__ w2l, const float* __restrict__ w2r,
                       const int* __restrict__ edge, int N,
                       int convx_blocks, int zero_blocks) {
    int b = blockIdx.x, tid = threadIdx.x;
    if (b < 128) {
        // weight transpose + hi/lo split: blocks [0,64) layer1, [64,128) layer2
        int layer = b >> 6;
        int t = (b & 63) * 256 + tid;            // 0..16383
        int k = t >> 7, n = t & 127;
        const float* Wl = layer ? w2l : w1l;
        const float* Wr = layer ? w2r : w1r;
        __nv_bfloat16* Bhi = layer ? g_B2hi : g_B1hi;
        __nv_bfloat16* Blo = layer ? g_B2lo : g_B1lo;
        __nv_bfloat16 h, l;
        split_bf(Wl[k * 128 + n], h, l);
        Bhi[n * 256 + k] = h; Blo[n * 256 + k] = l;
        split_bf(Wr[k * 128 + n], h, l);
        Bhi[n * 256 + 128 + k] = h; Blo[n * 256 + 128 + k] = l;
    } else if (b < 128 + convx_blocks) {
        // node_emb -> packed Xp (4 elems/thread)
        size_t i = ((size_t)(b - 128) * 256 + tid) * 4;
        if (i < (size_t)N * D) {
            float4 v = *reinterpret_cast<const float4*>(ne + i);
            uint4 p = make_uint4(packv(v.x), packv(v.y), packv(v.z), packv(v.w));
            *reinterpret_cast<uint4*>(g_Xp + i) = p;
        }
    } else if (b < 128 + convx_blocks + zero_blocks) {
        int i = (b - 128 - convx_blocks) * 256 + tid;
        if (i < N) g_cnt[i] = 0;
    } else {
        // int64-vs-int32 edge dtype detection
        int bad = (edge[2 * tid + 1] != 0) ? 1 : 0;
        bad = __syncthreads_or(bad);
        if (tid == 0) g_is64 = bad ? 0 : 1;
    }
}

// ================= CSR build =================
__global__ void k_convert_count(const int* __restrict__ p, int E) {
    int i = blockIdx.x * blockDim.x + threadIdx.x;
    if (i >= E) return;
    int s, d;
    if (g_is64) { s = p[2 * i]; d = p[2 * E + 2 * i]; }
    else        { s = p[i];     d = p[E + i]; }
    g_src[i] = s; g_dst[i] = d;
    atomicAdd(&g_cnt[d], 1);
}

#define SCAN_BLOCK 1024
__global__ void k_blocksum(int N) {
    __shared__ int sh[SCAN_BLOCK];
    int i = blockIdx.x * SCAN_BLOCK + threadIdx.x;
    sh[threadIdx.x] = (i < N) ? g_cnt[i] : 0;
    __syncthreads();
    for (int s = SCAN_BLOCK / 2; s > 0; s >>= 1) {
        if (threadIdx.x < s) sh[threadIdx.x] += sh[threadIdx.x + s];
        __syncthreads();
    }
    if (threadIdx.x == 0) g_bsum[blockIdx.x] = sh[0];
}

__global__ void k_scan_final(int N, int E, int nblk) {
    __shared__ int sh[SCAN_BLOCK];
    __shared__ int base;
    int i = blockIdx.x * SCAN_BLOCK + threadIdx.x;
    int v = (i < N) ? g_cnt[i] : 0;
    sh[threadIdx.x] = v;
    if (threadIdx.x == 0) {
        int run = 0;
        for (int bb = 0; bb < blockIdx.x; bb++) run += g_bsum[bb];
        base = run;
        if (blockIdx.x == nblk - 1) g_off[N] = E;
    }
    __syncthreads();
#pragma unroll
    for (int s = 1; s < SCAN_BLOCK; s <<= 1) {
        int t = (threadIdx.x >= s) ? sh[threadIdx.x - s] : 0;
        __syncthreads();
        sh[threadIdx.x] += t;
        __syncthreads();
    }
    if (i < N) {
        int excl = base + sh[threadIdx.x] - v;
        g_off[i] = excl;
        g_cursor[i] = excl;
    }
}

__global__ void k_fill(int E) {
    int i = blockIdx.x * blockDim.x + threadIdx.x;
    if (i >= E) return;
    int d = g_dst[i];
    g_csr[atomicAdd(&g_cursor[d], 1)] = g_src[i];
}

// ================= aggregation: CSR mean over packed rows -> packed Gp ==========
__global__ void k_aggr(const uint32_t* __restrict__ Xp, int N) {
    int warp = (blockIdx.x * blockDim.x + threadIdx.x) >> 5;
    if (warp >= N) return;
    int lane = threadIdx.x & 31;
    int beg = g_off[warp];
    int end = g_off[warp + 1];
    const int c = lane * 4;
    float4 acc = make_float4(0.f, 0.f, 0.f, 0.f);
    int i = beg;
    for (; i + 4 <= end; i += 4) {
        int s0 = g_csr[i], s1 = g_csr[i + 1], s2 = g_csr[i + 2], s3 = g_csr[i + 3];
        uint4 p0 = *reinterpret_cast<const uint4*>(Xp + (size_t)s0 * D + c);
        uint4 p1 = *reinterpret_cast<const uint4*>(Xp + (size_t)s1 * D + c);
        uint4 p2 = *reinterpret_cast<const uint4*>(Xp + (size_t)s2 * D + c);
        uint4 p3 = *reinterpret_cast<const uint4*>(Xp + (size_t)s3 * D + c);
        acc.x += unpackv(p0.x) + unpackv(p1.x) + unpackv(p2.x) + unpackv(p3.x);
        acc.y += unpackv(p0.y) + unpackv(p1.y) + unpackv(p2.y) + unpackv(p3.y);
        acc.z += unpackv(p0.z) + unpackv(p1.z) + unpackv(p2.z) + unpackv(p3.z);
        acc.w += unpackv(p0.w) + unpackv(p1.w) + unpackv(p2.w) + unpackv(p3.w);
    }
    for (; i < end; i++) {
        int s = g_csr[i];
        uint4 p = *reinterpret_cast<const uint4*>(Xp + (size_t)s * D + c);
        acc.x += unpackv(p.x); acc.y += unpackv(p.y);
        acc.z += unpackv(p.z); acc.w += unpackv(p.w);
    }
    int deg = end - beg;
    float inv = 1.f / (float)(deg > 0 ? deg : 1);
    uint4 o = make_uint4(packv(acc.x * inv), packv(acc.y * inv),
                         packv(acc.z * inv), packv(acc.w * inv));
    *reinterpret_cast<uint4*>(g_Gp + (size_t)warp * D + c) = o;
}

// ================= mma.sync GEMM =================
// A packed: chunk0 rows from Gp (aggr), chunk1 rows from Xp (x). B: [n][k] hi/lo bf16.
// D = Ahi.Bhi + Ahi.Blo + Alo.Bhi, fp32 accum. Tile 128x128.
#define GT 256
#define SAK 136
#define SROW (SAK * 2)                  // 272 B/row
#define CH_BYTES (128 * SROW)
#define OFF_AHI 0
#define OFF_ALO (CH_BYTES)
#define OFF_BHI (2 * CH_BYTES)
#define OFF_BLO (3 * CH_BYTES)
#define SM_TOTAL (4 * CH_BYTES)

__device__ __forceinline__ uint32_t smem_u32(const void* p) {
    uint32_t a;
    asm("{ .reg .u64 t; cvta.to.shared.u64 t, %1; cvt.u32.u64 %0, t; }" : "=r"(a) : "l"(p));
    return a;
}
__device__ __forceinline__ void ldsm_x4(uint32_t* r, uint32_t addr) {
    asm volatile("ldmatrix.sync.aligned.m8n8.x4.shared.b16 {%0,%1,%2,%3}, [%4];"
                 : "=r"(r[0]), "=r"(r[1]), "=r"(r[2]), "=r"(r[3]) : "r"(addr));
}
__device__ __forceinline__ void mma16816(float* c, const uint32_t* a, const uint32_t* b) {
    asm volatile(
        "mma.sync.aligned.m16n8k16.row.col.f32.bf16.bf16.f32 "
        "{%0,%1,%2,%3}, {%4,%5,%6,%7}, {%8,%9}, {%0,%1,%2,%3};"
        : "+f"(c[0]), "+f"(c[1]), "+f"(c[2]), "+f"(c[3])
        : "r"(a[0]), "r"(a[1]), "r"(a[2]), "r"(a[3]), "r"(b[0]), "r"(b[1]));
}

// OUTP: 1 -> relu + packed store to outp ; 0 -> fp32 store to outf
template <int OUTP>
__global__ void __launch_bounds__(GT, 1)
k_mma(const uint32_t* __restrict__ Ap0, const uint32_t* __restrict__ Ap1,
      const __nv_bfloat16* __restrict__ Bhi, const __nv_bfloat16* __restrict__ Blo,
      const float* __restrict__ bias, float* __restrict__ outf,
      uint32_t* __restrict__ outp, int N)
{
    extern __shared__ char smem[];
    const uint32_t sb = smem_u32(smem);
    const int tid = threadIdx.x;
    const int wid = tid >> 5, lane = tid & 31;
    const int wm = wid >> 1, wn = wid & 1;
    const int n0 = blockIdx.x * 128;

    float acc[2][8][4];
#pragma unroll
    for (int mf = 0; mf < 2; mf++)
#pragma unroll
        for (int nf = 0; nf < 8; nf++)
#pragma unroll
            for (int q = 0; q < 4; q++) acc[mf][nf][q] = 0.f;

    const int lrow = tid >> 1;
    const int lseg = tid & 1;

    const uint32_t a_off = (uint32_t)(wm * 32 + (lane & 15)) * SROW + (uint32_t)(lane >> 4) * 16;
    const uint32_t b_row = (uint32_t)(wn * 64 + (lane & 7) + (((lane >> 4) & 1) << 3));
    const uint32_t b_off = b_row * SROW + (uint32_t)((lane >> 3) & 1) * 16;

#pragma unroll
    for (int chunk = 0; chunk < 2; chunk++) {
        const int kofs = chunk * 128;
        const uint32_t* Ap = chunk ? Ap1 : Ap0;
        // ---- A: packed 128 uint32/row -> de-interleave into Ahi/Alo smem ----
        {
            int grow = n0 + lrow;
            bool valid = grow < N;
#pragma unroll
            for (int j = 0; j < 16; j++) {
                int idx16 = lseg * 16 + j;                 // 0..31 (16B packed units)
                uint4 p = valid ? *reinterpret_cast<const uint4*>(Ap + (size_t)grow * D + idx16 * 4)
                                : make_uint4(0, 0, 0, 0);
                uint32_t h0 = __byte_perm(p.x, p.y, 0x5410);
                uint32_t h1 = __byte_perm(p.z, p.w, 0x5410);
                uint32_t l0 = __byte_perm(p.x, p.y, 0x7632);
                uint32_t l1 = __byte_perm(p.z, p.w, 0x7632);
                uint32_t so = (uint32_t)lrow * SROW + (uint32_t)idx16 * 8;
                *reinterpret_cast<uint2*>(smem + OFF_AHI + so) = make_uint2(h0, h1);
                *reinterpret_cast<uint2*>(smem + OFF_ALO + so) = make_uint2(l0, l1);
            }
        }
        // ---- B: bf16 [128][256], chunk selects k-half ----
#pragma unroll
        for (int j = 0; j < 8; j++) {
            int c16 = lseg * 8 + j;
            uint32_t so = (uint32_t)lrow * SROW + (uint32_t)c16 * 16;
            size_t gb = (size_t)lrow * 256 + kofs + c16 * 8;
            *reinterpret_cast<uint4*>(smem + OFF_BHI + so) = *reinterpret_cast<const uint4*>(Bhi + gb);
            *reinterpret_cast<uint4*>(smem + OFF_BLO + so) = *reinterpret_cast<const uint4*>(Blo + gb);
        }
        __syncthreads();

#pragma unroll
        for (int term = 0; term < 3; term++) {
            const uint32_t sA = sb + (term == 2 ? OFF_ALO : OFF_AHI);
            const uint32_t sB = sb + (term == 1 ? OFF_BLO : OFF_BHI);
#pragma unroll
            for (int ks = 0; ks < 8; ks++) {
                const uint32_t kb = (uint32_t)ks * 32;
                uint32_t af[2][4];
                ldsm_x4(af[0], sA + a_off + kb);
                ldsm_x4(af[1], sA + a_off + 16 * SROW + kb);
                uint32_t bf[8][2];
#pragma unroll
                for (int nb = 0; nb < 4; nb++) {
                    uint32_t r[4];
                    ldsm_x4(r, sB + b_off + (uint32_t)nb * 16 * SROW + kb);
                    bf[nb * 2][0] = r[0]; bf[nb * 2][1] = r[1];
                    bf[nb * 2 + 1][0] = r[2]; bf[nb * 2 + 1][1] = r[3];
                }
#pragma unroll
                for (int mf = 0; mf < 2; mf++)
#pragma unroll
                    for (int nf = 0; nf < 8; nf++)
                        mma16816(acc[mf][nf], af[mf], bf[nf]);
            }
        }
        __syncthreads();
    }

    // ---- epilogue ----
    const int gid = lane >> 2, t4 = lane & 3;
#pragma unroll
    for (int nf = 0; nf < 8; nf++) {
        int col = wn * 64 + nf * 8 + t4 * 2;
        float b0 = __ldg(bias + col), b1 = __ldg(bias + col + 1);
#pragma unroll
        for (int mf = 0; mf < 2; mf++) {
#pragma unroll
            for (int h = 0; h < 2; h++) {
                int m = n0 + wm * 32 + mf * 16 + gid + h * 8;
                if (m < N) {
                    float ox = acc[mf][nf][2 * h + 0] + b0;
                    float oy = acc[mf][nf][2 * h + 1] + b1;
                    if (OUTP) {
                        ox = fmaxf(ox, 0.f); oy = fmaxf(oy, 0.f);
                        *reinterpret_cast<uint2*>(outp + (size_t)m * D + col) =
                            make_uint2(packv(ox), packv(oy));
                    } else {
                        *reinterpret_cast<float2*>(outf + (size_t)m * D + col) =
                            make_float2(ox, oy);
                    }
                }
            }
        }
    }
}

// ================= launch =================
extern "C" void kernel_launch(void* const* d_in, const int* in_sizes, int n_in,
                              void* d_out, int out_size) {
    const int*   edge     = (const int*)d_in[0];
    const float* node_emb = (const float*)d_in[1];
    const float* w1l      = (const float*)d_in[2];
    const float* b1       = (const float*)d_in[3];
    const float* w1r      = (const float*)d_in[4];
    const float* w2l      = (const float*)d_in[5];
    const float* b2       = (const float*)d_in[6];
    const float* w2r      = (const float*)d_in[7];
    float*       out      = (float*)d_out;

    const int E = in_sizes[0] / 2;
    const int N = in_sizes[1] / D;

    cudaFuncSetAttribute(k_mma<1>, cudaFuncAttributeMaxDynamicSharedMemorySize, SM_TOTAL);
    cudaFuncSetAttribute(k_mma<0>, cudaFuncAttributeMaxDynamicSharedMemorySize, SM_TOTAL);

    uint32_t *xp, *x2p, *gp;
    __nv_bfloat16 *b1hi, *b1lo, *b2hi, *b2lo;
    cudaGetSymbolAddress((void**)&xp,  g_Xp);
    cudaGetSymbolAddress((void**)&x2p, g_X2p);
    cudaGetSymbolAddress((void**)&gp,  g_Gp);
    cudaGetSymbolAddress((void**)&b1hi, g_B1hi);
    cudaGetSymbolAddress((void**)&b1lo, g_B1lo);
    cudaGetSymbolAddress((void**)&b2hi, g_B2hi);
    cudaGetSymbolAddress((void**)&b2lo, g_B2lo);

    const int nblk_scan = (N + SCAN_BLOCK - 1) / SCAN_BLOCK;
    const int tiles = (N + 127) / 128;
    const int aggr_blocks = (N * 32 + 255) / 256;
    const int convx_blocks = (N * 32 + 255) / 256;       // 4 elems/thread
    const int zero_blocks = (N + 255) / 256;
    const int prep_grid = 128 + convx_blocks + zero_blocks + 1;

    // launch #1..#5: prep + CSR build   (#6 = k_aggr -> what ncu -s 5 profiles)
    k_prep<<<prep_grid, 256>>>(node_emb, w1l, w1r, w2l, w2r, edge, N, convx_blocks, zero_blocks);
    k_convert_count<<<(E + 255) / 256, 256>>>(edge, E);
    k_blocksum<<<nblk_scan, SCAN_BLOCK>>>(N);
    k_scan_final<<<nblk_scan, SCAN_BLOCK>>>(N, E, nblk_scan);
    k_fill<<<(E + 255) / 256, 256>>>(E);

    // ---- layer 1 ----
    k_aggr<<<aggr_blocks, 256>>>(xp, N);
    k_mma<1><<<tiles, GT, SM_TOTAL>>>(gp, xp, b1hi, b1lo, b1, nullptr, x2p, N);

    // ---- layer 2 ----
    k_aggr<<<aggr_blocks, 256>>>(x2p, N);
    k_mma<0><<<tiles, GT, SM_TOTAL>>>(gp, x2p, b2hi, b2lo, b2, out, nullptr, N);
}